// round 8
// baseline (speedup 1.0000x reference)
#include <cuda_runtime.h>
#include <math.h>

// ===========================================================================
// Mamba3ScanBlock — N=65536, D_MODEL=8, D_INNER=16, D_STATE=16
//
// K0 prep : fused projections -> g_dtxb (dt, dt*xb), g_B, g_C, g_zx
// K1 scan : chunked parallel scan (CHUNK=32 + WARM=32). 1 warp = 1 chunk,
//           2 lanes/channel, 8 states/lane. SMEM 16-step tiles (batched
//           LDG.128 -> LDS-only inner loop). Coefficients: packed poly for
//           sin/cos, rcp via 2/(1-u)=rcp(0.5-0.5u), Ac/As formed scalar
//           (fmaf(cs,r2,-cs)) -> zero f32x2 pack MOVs. Branch-free full-tile
//           loops (no break inside unroll).
// ===========================================================================

#define MAXN   65536
#define CHUNK  32
#define WARM   32
#define WPB    4
#define TILE   16

__device__ __align__(16) float2 g_dtxb[MAXN * 16];  // (dt, dt*xb)
__device__ __align__(16) float  g_B   [MAXN * 16];
__device__ __align__(16) float  g_C   [MAXN * 16];
__device__ __align__(16) float2 g_zx  [MAXN * 16];  // (silu(z), D*xb)

typedef unsigned long long u64p;

__device__ __forceinline__ u64p pk2(float lo, float hi) {
    u64p r;
    unsigned int a = __float_as_uint(lo), b = __float_as_uint(hi);
    asm("mov.b64 %0, {%1, %2};" : "=l"(r) : "r"(a), "r"(b));
    return r;
}
__device__ __forceinline__ float plo(u64p v) {
    unsigned int a, b;
    asm("mov.b64 {%0, %1}, %2;" : "=r"(a), "=r"(b) : "l"(v));
    return __uint_as_float(a);
}
__device__ __forceinline__ float phi(u64p v) {
    unsigned int a, b;
    asm("mov.b64 {%0, %1}, %2;" : "=r"(a), "=r"(b) : "l"(v));
    return __uint_as_float(b);
}
__device__ __forceinline__ u64p fma2(u64p a, u64p b, u64p c) {
    u64p d; asm("fma.rn.f32x2 %0, %1, %2, %3;" : "=l"(d) : "l"(a), "l"(b), "l"(c));
    return d;
}
__device__ __forceinline__ u64p mul2(u64p a, u64p b) {
    u64p d; asm("mul.rn.f32x2 %0, %1, %2;" : "=l"(d) : "l"(a), "l"(b));
    return d;
}
__device__ __forceinline__ float frcp(float x) {
    float r; asm("rcp.approx.f32 %0, %1;" : "=f"(r) : "f"(x));
    return r;
}

// ---------------------------------------------------------------------------
// K0: prep — unchanged from round 7 (passing, ~fast enough)
// ---------------------------------------------------------------------------
__global__ void __launch_bounds__(256)
prep_kernel(const float* __restrict__ x,
            const float* __restrict__ in_w,
            const float* __restrict__ dt_w,
            const float* __restrict__ dt_b,
            const float* __restrict__ B_w,
            const float* __restrict__ C_w,
            const float* __restrict__ Dp,
            int N)
{
    __shared__ float s_in[256], s_dt[256], s_B[256], s_C[256], s_b[16], s_D[16];
    int tid = threadIdx.x;
    s_in[tid] = in_w[tid];
    s_dt[tid] = dt_w[tid];
    s_B[tid]  = B_w[tid];
    s_C[tid]  = C_w[tid];
    if (tid < 16) { s_b[tid] = dt_b[tid]; s_D[tid] = Dp[tid]; }
    __syncthreads();

    int gid = blockIdx.x * 256 + tid;
    int t0 = gid * 2;
    if (t0 >= N) return;
    int t1 = (t0 + 1 < N) ? t0 + 1 : t0;

    float4 xa0 = __ldg((const float4*)(x + (size_t)t0 * 8));
    float4 xb0 = __ldg((const float4*)(x + (size_t)t0 * 8 + 4));
    float4 xa1 = __ldg((const float4*)(x + (size_t)t1 * 8));
    float4 xb1 = __ldg((const float4*)(x + (size_t)t1 * 8 + 4));

    float v0[16], v1[16];
    #pragma unroll
    for (int m = 0; m < 16; m++) {
        float4 wa = ((const float4*)s_in)[2 * m];
        float4 wb = ((const float4*)s_in)[2 * m + 1];
        v0[m] = fmaf(wa.x, xa0.x, fmaf(wa.y, xa0.y, fmaf(wa.z, xa0.z, fmaf(wa.w, xa0.w,
                fmaf(wb.x, xb0.x, fmaf(wb.y, xb0.y, fmaf(wb.z, xb0.z, wb.w * xb0.w)))))));
        v1[m] = fmaf(wa.x, xa1.x, fmaf(wa.y, xa1.y, fmaf(wa.z, xa1.z, fmaf(wa.w, xa1.w,
                fmaf(wb.x, xb1.x, fmaf(wb.y, xb1.y, fmaf(wb.z, xb1.z, wb.w * xb1.w)))))));
    }

    size_t base0 = (size_t)t0 * 16, base1 = (size_t)t1 * 16;

    #pragma unroll
    for (int m = 0; m < 16; m += 2) {
        float z[2][2];
        #pragma unroll
        for (int mm = 0; mm < 2; mm++) {
            float4 wa = ((const float4*)s_in)[32 + 2 * (m + mm)];
            float4 wb = ((const float4*)s_in)[33 + 2 * (m + mm)];
            z[mm][0] = fmaf(wa.x, xa0.x, fmaf(wa.y, xa0.y, fmaf(wa.z, xa0.z, fmaf(wa.w, xa0.w,
                       fmaf(wb.x, xb0.x, fmaf(wb.y, xb0.y, fmaf(wb.z, xb0.z, wb.w * xb0.w)))))));
            z[mm][1] = fmaf(wa.x, xa1.x, fmaf(wa.y, xa1.y, fmaf(wa.z, xa1.z, fmaf(wa.w, xa1.w,
                       fmaf(wb.x, xb1.x, fmaf(wb.y, xb1.y, fmaf(wb.z, xb1.z, wb.w * xb1.w)))))));
        }
        float zs00 = z[0][0] * frcp(1.0f + __expf(-z[0][0]));
        float zs10 = z[1][0] * frcp(1.0f + __expf(-z[1][0]));
        float zs01 = z[0][1] * frcp(1.0f + __expf(-z[0][1]));
        float zs11 = z[1][1] * frcp(1.0f + __expf(-z[1][1]));
        *((float4*)(g_zx + base0 + m)) = make_float4(zs00, s_D[m] * v0[m], zs10, s_D[m+1] * v0[m+1]);
        *((float4*)(g_zx + base1 + m)) = make_float4(zs01, s_D[m] * v1[m], zs11, s_D[m+1] * v1[m+1]);
    }

    #pragma unroll
    for (int i = 0; i < 16; i += 2) {
        float a00 = s_b[i], a01 = s_b[i], a10 = s_b[i+1], a11 = s_b[i+1];
        #pragma unroll
        for (int q = 0; q < 4; q++) {
            float4 w0 = ((const float4*)s_dt)[i * 4 + q];
            float4 w1 = ((const float4*)s_dt)[(i + 1) * 4 + q];
            a00 = fmaf(w0.x, v0[4*q], fmaf(w0.y, v0[4*q+1], fmaf(w0.z, v0[4*q+2], fmaf(w0.w, v0[4*q+3], a00))));
            a01 = fmaf(w0.x, v1[4*q], fmaf(w0.y, v1[4*q+1], fmaf(w0.z, v1[4*q+2], fmaf(w0.w, v1[4*q+3], a01))));
            a10 = fmaf(w1.x, v0[4*q], fmaf(w1.y, v0[4*q+1], fmaf(w1.z, v0[4*q+2], fmaf(w1.w, v0[4*q+3], a10))));
            a11 = fmaf(w1.x, v1[4*q], fmaf(w1.y, v1[4*q+1], fmaf(w1.z, v1[4*q+2], fmaf(w1.w, v1[4*q+3], a11))));
        }
        float d00 = (a00 > 15.0f) ? a00 : __logf(1.0f + __expf(a00));
        float d01 = (a01 > 15.0f) ? a01 : __logf(1.0f + __expf(a01));
        float d10 = (a10 > 15.0f) ? a10 : __logf(1.0f + __expf(a10));
        float d11 = (a11 > 15.0f) ? a11 : __logf(1.0f + __expf(a11));
        *((float4*)(g_dtxb + base0 + i)) = make_float4(d00, d00 * v0[i], d10, d10 * v0[i+1]);
        *((float4*)(g_dtxb + base1 + i)) = make_float4(d01, d01 * v1[i], d11, d11 * v1[i+1]);
    }

    #pragma unroll
    for (int j = 0; j < 16; j += 4) {
        float b0[4], b1[4], c0[4], c1[4];
        #pragma unroll
        for (int r = 0; r < 4; r++) {
            float bb0 = 0.f, bb1 = 0.f, cc0 = 0.f, cc1 = 0.f;
            #pragma unroll
            for (int q = 0; q < 4; q++) {
                float4 wB = ((const float4*)s_B)[(j + r) * 4 + q];
                float4 wC = ((const float4*)s_C)[(j + r) * 4 + q];
                bb0 = fmaf(wB.x, v0[4*q], fmaf(wB.y, v0[4*q+1], fmaf(wB.z, v0[4*q+2], fmaf(wB.w, v0[4*q+3], bb0))));
                bb1 = fmaf(wB.x, v1[4*q], fmaf(wB.y, v1[4*q+1], fmaf(wB.z, v1[4*q+2], fmaf(wB.w, v1[4*q+3], bb1))));
                cc0 = fmaf(wC.x, v0[4*q], fmaf(wC.y, v0[4*q+1], fmaf(wC.z, v0[4*q+2], fmaf(wC.w, v0[4*q+3], cc0))));
                cc1 = fmaf(wC.x, v1[4*q], fmaf(wC.y, v1[4*q+1], fmaf(wC.z, v1[4*q+2], fmaf(wC.w, v1[4*q+3], cc1))));
            }
            b0[r] = bb0; b1[r] = bb1; c0[r] = cc0; c1[r] = cc1;
        }
        *((float4*)(g_B + base0 + j)) = make_float4(b0[0], b0[1], b0[2], b0[3]);
        *((float4*)(g_B + base1 + j)) = make_float4(b1[0], b1[1], b1[2], b1[3]);
        *((float4*)(g_C + base0 + j)) = make_float4(c0[0], c0[1], c0[2], c0[3]);
        *((float4*)(g_C + base1 + j)) = make_float4(c1[0], c1[1], c1[2], c1[3]);
    }
}

// ---------------------------------------------------------------------------
// K1: scan + fused output projection.
// ---------------------------------------------------------------------------
__global__ void __launch_bounds__(32 * WPB)
scan_kernel(const float* __restrict__ A_log,
            const float* __restrict__ rf,
            const float* __restrict__ h0,
            const float* __restrict__ ow,
            float* __restrict__ d_out,
            int N, int nchunks, int write_hfinal)
{
    __shared__ float4 stile[WPB][TILE][16];
    __shared__ float  sy[WPB][CHUNK * 17];
    __shared__ float  sow[128];

    const int tid  = threadIdx.x;
    const int lane = tid & 31;
    const int w    = tid >> 5;
    sow[tid] = __ldg(ow + tid);
    __syncthreads();

    const int chunk = blockIdx.x * WPB + w;
    if (chunk >= nchunks) return;

    const int ch = lane >> 1;
    const int p  = lane & 1;
    const int cidx = ch * 16 + p * 8;

    u64p Ah[4], Rf[4];
    {
        float4 av0 = __ldg((const float4*)(A_log + cidx));
        float4 av1 = __ldg((const float4*)(A_log + cidx + 4));
        float4 rv0 = __ldg((const float4*)(rf + cidx));
        float4 rv1 = __ldg((const float4*)(rf + cidx + 4));
        Ah[0] = pk2(-0.5f * __expf(av0.x), -0.5f * __expf(av0.y));
        Ah[1] = pk2(-0.5f * __expf(av0.z), -0.5f * __expf(av0.w));
        Ah[2] = pk2(-0.5f * __expf(av1.x), -0.5f * __expf(av1.y));
        Ah[3] = pk2(-0.5f * __expf(av1.z), -0.5f * __expf(av1.w));
        Rf[0] = pk2(rv0.x, rv0.y);
        Rf[1] = pk2(rv0.z, rv0.w);
        Rf[2] = pk2(rv1.x, rv1.y);
        Rf[3] = pk2(rv1.z, rv1.w);
    }
    const u64p ONE  = pk2(1.0f, 1.0f);
    const u64p NEG1 = pk2(-1.0f, -1.0f);
    const u64p K6   = pk2(1.0f/6.0f, 1.0f/6.0f);
    const u64p K24  = pk2(1.0f/24.0f, 1.0f/24.0f);
    const u64p Kn05 = pk2(-0.5f, -0.5f);
    const u64p Kp05 = pk2(0.5f, 0.5f);

    const int t_main  = chunk * CHUNK;
    const int mainlen = (N - t_main < CHUNK) ? (N - t_main) : CHUNK;

    float h[8];
    if (chunk <= 1) {   // chunk 0: no warm; chunk 1: warm spans full prefix -> exact h0 start
        float4 a = __ldg((const float4*)(h0 + cidx));
        float4 b = __ldg((const float4*)(h0 + cidx + 4));
        h[0]=a.x; h[1]=a.y; h[2]=a.z; h[3]=a.w;
        h[4]=b.x; h[5]=b.y; h[6]=b.z; h[7]=b.w;
    } else {
        #pragma unroll
        for (int j = 0; j < 8; j++) h[j] = 0.f;
    }

    float4 (*tile)[16] = stile[w];

    // ---- staging: full 16-step tile, unguarded ----
    auto stage_full = [&](int t0, bool withC) {
        const float4* src_d = (const float4*)(g_dtxb + (size_t)t0 * 16);
        const float4* src_B = (const float4*)(g_B    + (size_t)t0 * 16);
        const float4* src_C = (const float4*)(g_C    + (size_t)t0 * 16);
        __syncwarp();
        #pragma unroll
        for (int r = 0; r < 4; r++) {
            int idx = lane + 32 * r;
            tile[idx >> 3][idx & 7] = __ldg(src_d + idx);
        }
        #pragma unroll
        for (int r = 0; r < 2; r++) {
            int idx = lane + 32 * r;
            tile[idx >> 2][8 + (idx & 3)] = __ldg(src_B + idx);
            if (withC) tile[idx >> 2][12 + (idx & 3)] = __ldg(src_C + idx);
        }
        __syncwarp();
    };

    // ---- one recurrence step from tile record i ----
    // coefficients: r2 = 2/(1-u) via rcp(0.5-0.5u); Ac = cs*(r2-1), As = sn*(r2-1)
    float AcS[8], AsS[8];
    auto step_h = [&](int i) {
        const float* rec = (const float*)tile[i];
        float2 dx = *(const float2*)(rec + ch * 2);
        float4 B0 = *(const float4*)(rec + 32 + p * 8);
        float4 B1 = *(const float4*)(rec + 36 + p * 8);
        const float dt = dx.x;
        const u64p dtp = pk2(dt, dt);
        #pragma unroll
        for (int q = 0; q < 4; q++) {
            u64p u   = mul2(dtp, Ah[q]);
            u64p omh = fma2(u, Kn05, Kp05);          // 0.5 - 0.5u
            float r2l = frcp(plo(omh));              // 2/(1-u)
            float r2h = frcp(phi(omh));
            u64p a  = mul2(dtp, Rf[q]);
            u64p qq = mul2(a, a);
            u64p sn = mul2(a, fma2(qq, K6, NEG1));   // -sin
            u64p cs = fma2(qq, fma2(qq, K24, Kn05), ONE);
            float csl = plo(cs), csh = phi(cs);
            float snl = plo(sn), snh = phi(sn);
            AcS[2*q]   = fmaf(csl, r2l, -csl);       // cs*(r2-1)
            AcS[2*q+1] = fmaf(csh, r2h, -csh);
            AsS[2*q]   = fmaf(snl, r2l, -snl);       // -sin*(r2-1)
            AsS[2*q+1] = fmaf(snh, r2h, -snh);
        }
        const float db = dx.y;                       // dt*xb prefolded
        const float wrap = __shfl_xor_sync(0xffffffffu, h[7], 1);
        h[7] = fmaf(AcS[7], h[7], fmaf(AsS[7], h[6], db * B1.w));
        h[6] = fmaf(AcS[6], h[6], fmaf(AsS[6], h[5], db * B1.z));
        h[5] = fmaf(AcS[5], h[5], fmaf(AsS[5], h[4], db * B1.y));
        h[4] = fmaf(AcS[4], h[4], fmaf(AsS[4], h[3], db * B1.x));
        h[3] = fmaf(AcS[3], h[3], fmaf(AsS[3], h[2], db * B0.w));
        h[2] = fmaf(AcS[2], h[2], fmaf(AsS[2], h[1], db * B0.z));
        h[1] = fmaf(AcS[1], h[1], fmaf(AsS[1], h[0], db * B0.y));
        h[0] = fmaf(AcS[0], h[0], fmaf(AsS[0], wrap, db * B0.x));
    };

    auto emit_y = [&](int i, int m) {
        const float* rec = (const float*)tile[i];
        float4 C0 = *(const float4*)(rec + 48 + p * 8);
        float4 C1 = *(const float4*)(rec + 52 + p * 8);
        float y0 = C0.x * h[0];
        float y1 = C0.y * h[1];
        y0 = fmaf(C0.z, h[2], y0);
        y1 = fmaf(C0.w, h[3], y1);
        y0 = fmaf(C1.x, h[4], y0);
        y1 = fmaf(C1.y, h[5], y1);
        y0 = fmaf(C1.z, h[6], y0);
        y1 = fmaf(C1.w, h[7], y1);
        float y = y0 + y1;
        y += __shfl_xor_sync(0xffffffffu, y, 1);
        if (p == 0) sy[w][m * 17 + ch] = y;
    };

    // ---- warm-up: exactly 2 full tiles for chunk >= 1 ----
    if (chunk >= 1) {
        const int t_w = t_main - WARM;
        stage_full(t_w, false);
        #pragma unroll 4
        for (int i = 0; i < TILE; ++i) step_h(i);
        stage_full(t_w + TILE, false);
        #pragma unroll 4
        for (int i = 0; i < TILE; ++i) step_h(i);
    }

    // ---- main ----
    if (mainlen == CHUNK) {
        stage_full(t_main, true);
        #pragma unroll 4
        for (int i = 0; i < TILE; ++i) { step_h(i); emit_y(i, i); }
        stage_full(t_main + TILE, true);
        #pragma unroll 4
        for (int i = 0; i < TILE; ++i) { step_h(i); emit_y(i, TILE + i); }
    } else {
        // generic tail (N not multiple of CHUNK)
        for (int m0 = 0; m0 < mainlen; m0 += TILE) {
            int cnt = mainlen - m0; if (cnt > TILE) cnt = TILE;
            // guarded staging
            {
                const float4* src_d = (const float4*)(g_dtxb + (size_t)(t_main + m0) * 16);
                const float4* src_B = (const float4*)(g_B    + (size_t)(t_main + m0) * 16);
                const float4* src_C = (const float4*)(g_C    + (size_t)(t_main + m0) * 16);
                __syncwarp();
                for (int r = 0; r < 4; r++) {
                    int idx = lane + 32 * r;
                    if (idx < cnt * 8) tile[idx >> 3][idx & 7] = __ldg(src_d + idx);
                }
                for (int r = 0; r < 2; r++) {
                    int idx = lane + 32 * r;
                    if (idx < cnt * 4) {
                        tile[idx >> 2][8  + (idx & 3)] = __ldg(src_B + idx);
                        tile[idx >> 2][12 + (idx & 3)] = __ldg(src_C + idx);
                    }
                }
                __syncwarp();
            }
            for (int i = 0; i < cnt; ++i) { step_h(i); emit_y(i, m0 + i); }
        }
    }

    // ---- final state ----
    if (write_hfinal && chunk == nchunks - 1) {
        float* o = d_out + (size_t)N * 8 + cidx;
        ((float4*)o)[0] = make_float4(h[0], h[1], h[2], h[3]);
        ((float4*)o)[1] = make_float4(h[4], h[5], h[6], h[7]);
    }

    __syncwarp();

    // ---- warp-private fused output projection ----
    if (lane < mainlen) {
        int t = t_main + lane;
        const float4* z4 = (const float4*)(g_zx + (size_t)t * 16);
        const float* syr = &sy[w][lane * 17];
        float v[16];
        #pragma unroll
        for (int q = 0; q < 4; q++) {
            float4 za = __ldg(z4 + 2 * q);
            float4 zb = __ldg(z4 + 2 * q + 1);
            v[4*q+0] = fmaf(syr[4*q+0], za.x, za.y);
            v[4*q+1] = fmaf(syr[4*q+1], za.z, za.w);
            v[4*q+2] = fmaf(syr[4*q+2], zb.x, zb.y);
            v[4*q+3] = fmaf(syr[4*q+3], zb.z, zb.w);
        }
        float o[8];
        #pragma unroll
        for (int d = 0; d < 8; d++) {
            float acc = 0.f;
            #pragma unroll
            for (int q = 0; q < 4; q++) {
                float4 wr = ((const float4*)sow)[d * 4 + q];
                acc = fmaf(wr.x, v[4*q+0], fmaf(wr.y, v[4*q+1],
                      fmaf(wr.z, v[4*q+2], fmaf(wr.w, v[4*q+3], acc))));
            }
            o[d] = acc;
        }
        ((float4*)(d_out + (size_t)t * 8))[0] = make_float4(o[0], o[1], o[2], o[3]);
        ((float4*)(d_out + (size_t)t * 8))[1] = make_float4(o[4], o[5], o[6], o[7]);
    }
}

// ---------------------------------------------------------------------------
extern "C" void kernel_launch(void* const* d_in, const int* in_sizes, int n_in,
                              void* d_out, int out_size)
{
    const float* x    = (const float*)d_in[0];
    const float* h0   = (const float*)d_in[1];
    const float* inw  = (const float*)d_in[2];
    const float* dtw  = (const float*)d_in[3];
    const float* dtb  = (const float*)d_in[4];
    const float* Bw   = (const float*)d_in[5];
    const float* Cw   = (const float*)d_in[6];
    const float* Alog = (const float*)d_in[7];
    const float* Dp   = (const float*)d_in[8];
    const float* rf   = (const float*)d_in[9];
    const float* ow   = (const float*)d_in[10];

    int N = in_sizes[0] / 8;
    if (N > MAXN) N = MAXN;
    int nchunks = (N + CHUNK - 1) / CHUNK;
    int write_hfinal = (out_size >= N * 8 + 256) ? 1 : 0;

    prep_kernel<<<(N / 2 + 255) / 256, 256>>>(x, inw, dtw, dtb, Bw, Cw, Dp, N);
    scan_kernel<<<(nchunks + WPB - 1) / WPB, 32 * WPB>>>(Alog, rf, h0, ow,
                                                         (float*)d_out, N, nchunks, write_hfinal);
}

// round 9
// speedup vs baseline: 1.0898x; 1.0898x over previous
#include <cuda_runtime.h>
#include <math.h>

// ===========================================================================
// Mamba3ScanBlock — N=65536, D_MODEL=8, D_INNER=16, D_STATE=16
//
// K0 prep : fused projections -> g_dtxb (dt, dt*xb), g_B, g_C, g_zx
// K1 scan : chunked parallel scan (CHUNK=64 + WARM=32 contraction warm-up,
//           1024 warps). 1 warp = 1 chunk, 2 lanes/channel, 8 states/lane.
//           ALL-SCALAR step math (no f32x2 / no inline-asm movs):
//             omh = fma(dt, A/4, 0.5)  -> r2 = rcp(omh) = 2/(1-u)
//             Ac  = fma(cs, r2, -cs)   = Abar*cos,  As = fma(sn, r2, -sn)
//           Inputs flow through cp.async double-buffered 8-step SMEM tiles
//           (no register staging, LDG latency hidden behind compute).
// ===========================================================================

#define MAXN   65536
#define CHUNK  64
#define WARM   32
#define WPB    4
#define TILE   8

__device__ __align__(16) float2 g_dtxb[MAXN * 16];  // (dt, dt*xb)
__device__ __align__(16) float  g_B   [MAXN * 16];
__device__ __align__(16) float  g_C   [MAXN * 16];
__device__ __align__(16) float2 g_zx  [MAXN * 16];  // (silu(z), D*xb)

__device__ __forceinline__ float frcp(float x) {
    float r; asm("rcp.approx.f32 %0, %1;" : "=f"(r) : "f"(x));
    return r;
}
__device__ __forceinline__ void cp_async16(void* smem_dst, const void* gmem_src) {
    unsigned dst = (unsigned)__cvta_generic_to_shared(smem_dst);
    asm volatile("cp.async.cg.shared.global [%0], [%1], 16;" :: "r"(dst), "l"(gmem_src) : "memory");
}
__device__ __forceinline__ void cp_commit() {
    asm volatile("cp.async.commit_group;" ::: "memory");
}
template <int n>
__device__ __forceinline__ void cp_wait() {
    asm volatile("cp.async.wait_group %0;" :: "n"(n) : "memory");
}

// ---------------------------------------------------------------------------
// K0: prep — unchanged (passing)
// ---------------------------------------------------------------------------
__global__ void __launch_bounds__(256)
prep_kernel(const float* __restrict__ x,
            const float* __restrict__ in_w,
            const float* __restrict__ dt_w,
            const float* __restrict__ dt_b,
            const float* __restrict__ B_w,
            const float* __restrict__ C_w,
            const float* __restrict__ Dp,
            int N)
{
    __shared__ float s_in[256], s_dt[256], s_B[256], s_C[256], s_b[16], s_D[16];
    int tid = threadIdx.x;
    s_in[tid] = in_w[tid];
    s_dt[tid] = dt_w[tid];
    s_B[tid]  = B_w[tid];
    s_C[tid]  = C_w[tid];
    if (tid < 16) { s_b[tid] = dt_b[tid]; s_D[tid] = Dp[tid]; }
    __syncthreads();

    int gid = blockIdx.x * 256 + tid;
    int t0 = gid * 2;
    if (t0 >= N) return;
    int t1 = (t0 + 1 < N) ? t0 + 1 : t0;

    float4 xa0 = __ldg((const float4*)(x + (size_t)t0 * 8));
    float4 xb0 = __ldg((const float4*)(x + (size_t)t0 * 8 + 4));
    float4 xa1 = __ldg((const float4*)(x + (size_t)t1 * 8));
    float4 xb1 = __ldg((const float4*)(x + (size_t)t1 * 8 + 4));

    float v0[16], v1[16];
    #pragma unroll
    for (int m = 0; m < 16; m++) {
        float4 wa = ((const float4*)s_in)[2 * m];
        float4 wb = ((const float4*)s_in)[2 * m + 1];
        v0[m] = fmaf(wa.x, xa0.x, fmaf(wa.y, xa0.y, fmaf(wa.z, xa0.z, fmaf(wa.w, xa0.w,
                fmaf(wb.x, xb0.x, fmaf(wb.y, xb0.y, fmaf(wb.z, xb0.z, wb.w * xb0.w)))))));
        v1[m] = fmaf(wa.x, xa1.x, fmaf(wa.y, xa1.y, fmaf(wa.z, xa1.z, fmaf(wa.w, xa1.w,
                fmaf(wb.x, xb1.x, fmaf(wb.y, xb1.y, fmaf(wb.z, xb1.z, wb.w * xb1.w)))))));
    }

    size_t base0 = (size_t)t0 * 16, base1 = (size_t)t1 * 16;

    #pragma unroll
    for (int m = 0; m < 16; m += 2) {
        float z[2][2];
        #pragma unroll
        for (int mm = 0; mm < 2; mm++) {
            float4 wa = ((const float4*)s_in)[32 + 2 * (m + mm)];
            float4 wb = ((const float4*)s_in)[33 + 2 * (m + mm)];
            z[mm][0] = fmaf(wa.x, xa0.x, fmaf(wa.y, xa0.y, fmaf(wa.z, xa0.z, fmaf(wa.w, xa0.w,
                       fmaf(wb.x, xb0.x, fmaf(wb.y, xb0.y, fmaf(wb.z, xb0.z, wb.w * xb0.w)))))));
            z[mm][1] = fmaf(wa.x, xa1.x, fmaf(wa.y, xa1.y, fmaf(wa.z, xa1.z, fmaf(wa.w, xa1.w,
                       fmaf(wb.x, xb1.x, fmaf(wb.y, xb1.y, fmaf(wb.z, xb1.z, wb.w * xb1.w)))))));
        }
        float zs00 = z[0][0] * frcp(1.0f + __expf(-z[0][0]));
        float zs10 = z[1][0] * frcp(1.0f + __expf(-z[1][0]));
        float zs01 = z[0][1] * frcp(1.0f + __expf(-z[0][1]));
        float zs11 = z[1][1] * frcp(1.0f + __expf(-z[1][1]));
        *((float4*)(g_zx + base0 + m)) = make_float4(zs00, s_D[m] * v0[m], zs10, s_D[m+1] * v0[m+1]);
        *((float4*)(g_zx + base1 + m)) = make_float4(zs01, s_D[m] * v1[m], zs11, s_D[m+1] * v1[m+1]);
    }

    #pragma unroll
    for (int i = 0; i < 16; i += 2) {
        float a00 = s_b[i], a01 = s_b[i], a10 = s_b[i+1], a11 = s_b[i+1];
        #pragma unroll
        for (int q = 0; q < 4; q++) {
            float4 w0 = ((const float4*)s_dt)[i * 4 + q];
            float4 w1 = ((const float4*)s_dt)[(i + 1) * 4 + q];
            a00 = fmaf(w0.x, v0[4*q], fmaf(w0.y, v0[4*q+1], fmaf(w0.z, v0[4*q+2], fmaf(w0.w, v0[4*q+3], a00))));
            a01 = fmaf(w0.x, v1[4*q], fmaf(w0.y, v1[4*q+1], fmaf(w0.z, v1[4*q+2], fmaf(w0.w, v1[4*q+3], a01))));
            a10 = fmaf(w1.x, v0[4*q], fmaf(w1.y, v0[4*q+1], fmaf(w1.z, v0[4*q+2], fmaf(w1.w, v0[4*q+3], a10))));
            a11 = fmaf(w1.x, v1[4*q], fmaf(w1.y, v1[4*q+1], fmaf(w1.z, v1[4*q+2], fmaf(w1.w, v1[4*q+3], a11))));
        }
        float d00 = (a00 > 15.0f) ? a00 : __logf(1.0f + __expf(a00));
        float d01 = (a01 > 15.0f) ? a01 : __logf(1.0f + __expf(a01));
        float d10 = (a10 > 15.0f) ? a10 : __logf(1.0f + __expf(a10));
        float d11 = (a11 > 15.0f) ? a11 : __logf(1.0f + __expf(a11));
        *((float4*)(g_dtxb + base0 + i)) = make_float4(d00, d00 * v0[i], d10, d10 * v0[i+1]);
        *((float4*)(g_dtxb + base1 + i)) = make_float4(d01, d01 * v1[i], d11, d11 * v1[i+1]);
    }

    #pragma unroll
    for (int j = 0; j < 16; j += 4) {
        float b0[4], b1[4], c0[4], c1[4];
        #pragma unroll
        for (int r = 0; r < 4; r++) {
            float bb0 = 0.f, bb1 = 0.f, cc0 = 0.f, cc1 = 0.f;
            #pragma unroll
            for (int q = 0; q < 4; q++) {
                float4 wB = ((const float4*)s_B)[(j + r) * 4 + q];
                float4 wC = ((const float4*)s_C)[(j + r) * 4 + q];
                bb0 = fmaf(wB.x, v0[4*q], fmaf(wB.y, v0[4*q+1], fmaf(wB.z, v0[4*q+2], fmaf(wB.w, v0[4*q+3], bb0))));
                bb1 = fmaf(wB.x, v1[4*q], fmaf(wB.y, v1[4*q+1], fmaf(wB.z, v1[4*q+2], fmaf(wB.w, v1[4*q+3], bb1))));
                cc0 = fmaf(wC.x, v0[4*q], fmaf(wC.y, v0[4*q+1], fmaf(wC.z, v0[4*q+2], fmaf(wC.w, v0[4*q+3], cc0))));
                cc1 = fmaf(wC.x, v1[4*q], fmaf(wC.y, v1[4*q+1], fmaf(wC.z, v1[4*q+2], fmaf(wC.w, v1[4*q+3], cc1))));
            }
            b0[r] = bb0; b1[r] = bb1; c0[r] = cc0; c1[r] = cc1;
        }
        *((float4*)(g_B + base0 + j)) = make_float4(b0[0], b0[1], b0[2], b0[3]);
        *((float4*)(g_B + base1 + j)) = make_float4(b1[0], b1[1], b1[2], b1[3]);
        *((float4*)(g_C + base0 + j)) = make_float4(c0[0], c0[1], c0[2], c0[3]);
        *((float4*)(g_C + base1 + j)) = make_float4(c1[0], c1[1], c1[2], c1[3]);
    }
}

// ---------------------------------------------------------------------------
// K1: scan + fused output projection. 1 warp = 1 chunk.
//   Tile record per step: float4[16] = [0:8) dtxb, [8:12) B, [12:16) C.
// ---------------------------------------------------------------------------
__global__ void __launch_bounds__(32 * WPB)
scan_kernel(const float* __restrict__ A_log,
            const float* __restrict__ rf,
            const float* __restrict__ h0,
            const float* __restrict__ ow,
            float* __restrict__ d_out,
            int N, int nchunks, int write_hfinal)
{
    __shared__ float4 stile[WPB][2][TILE][16];     // double-buffered 8-step tiles
    __shared__ float  sy[WPB][CHUNK * 17];
    __shared__ float  sow[128];

    const int tid  = threadIdx.x;
    const int lane = tid & 31;
    const int w    = tid >> 5;
    sow[tid] = __ldg(ow + tid);
    __syncthreads();

    const int chunk = blockIdx.x * WPB + w;
    if (chunk >= nchunks) return;

    const int ch = lane >> 1;
    const int p  = lane & 1;
    const int cidx = ch * 16 + p * 8;

    // per-lane constants: Aq = exp(A_log)/4 (so omh = fma(dt, Aq, 0.5) = 0.5-0.5u)
    float Aq[8], Rfs[8];
    {
        float4 av0 = __ldg((const float4*)(A_log + cidx));
        float4 av1 = __ldg((const float4*)(A_log + cidx + 4));
        float4 rv0 = __ldg((const float4*)(rf + cidx));
        float4 rv1 = __ldg((const float4*)(rf + cidx + 4));
        Aq[0] = 0.25f * __expf(av0.x); Aq[1] = 0.25f * __expf(av0.y);
        Aq[2] = 0.25f * __expf(av0.z); Aq[3] = 0.25f * __expf(av0.w);
        Aq[4] = 0.25f * __expf(av1.x); Aq[5] = 0.25f * __expf(av1.y);
        Aq[6] = 0.25f * __expf(av1.z); Aq[7] = 0.25f * __expf(av1.w);
        Rfs[0] = rv0.x; Rfs[1] = rv0.y; Rfs[2] = rv0.z; Rfs[3] = rv0.w;
        Rfs[4] = rv1.x; Rfs[5] = rv1.y; Rfs[6] = rv1.z; Rfs[7] = rv1.w;
    }

    const int t_main  = chunk * CHUNK;
    const int mainlen = (N - t_main < CHUNK) ? (N - t_main) : CHUNK;
    const int warmtiles = (chunk == 0) ? 0 : (WARM / TILE);   // 0 or 4
    const int t_begin = t_main - warmtiles * TILE;

    float h[8];
    if (chunk == 0) {
        float4 a = __ldg((const float4*)(h0 + cidx));
        float4 b = __ldg((const float4*)(h0 + cidx + 4));
        h[0]=a.x; h[1]=a.y; h[2]=a.z; h[3]=a.w;
        h[4]=b.x; h[5]=b.y; h[6]=b.z; h[7]=b.w;
    } else {
        #pragma unroll
        for (int j = 0; j < 8; j++) h[j] = 0.f;
    }

    // async-stage one 8-step tile into buffer buf (4 cp.async of 16B per lane)
    auto stage = [&](int buf, int t0) {
        const float4* src_d = (const float4*)(g_dtxb + (size_t)t0 * 16);  // 64 float4
        const float4* src_B = (const float4*)(g_B    + (size_t)t0 * 16);  // 32 float4
        const float4* src_C = (const float4*)(g_C    + (size_t)t0 * 16);  // 32 float4
        float4 (*tl)[16] = stile[w][buf];
        #pragma unroll
        for (int r = 0; r < 2; r++) {
            int idx = lane + 32 * r;
            cp_async16(&tl[idx >> 3][idx & 7], src_d + idx);
        }
        cp_async16(&tl[lane >> 2][8  + (lane & 3)], src_B + lane);
        cp_async16(&tl[lane >> 2][12 + (lane & 3)], src_C + lane);
        cp_commit();
    };

    // one scalar recurrence step from record rec
    auto step_h = [&](const float* rec) {
        float2 dx = *(const float2*)(rec + ch * 2);
        float4 B0 = *(const float4*)(rec + 32 + p * 8);
        float4 B1 = *(const float4*)(rec + 36 + p * 8);
        const float dt = dx.x, db = dx.y;
        float Ac[8], As[8];
        #pragma unroll
        for (int s = 0; s < 8; s++) {
            float omh = fmaf(dt, Aq[s], 0.5f);            // 0.5 - 0.5u
            float r2  = frcp(omh);                        // 2/(1-u); Abar = r2-1
            float a   = dt * Rfs[s];
            float qq  = a * a;
            float sn  = a * fmaf(qq, 1.0f/6.0f, -1.0f);   // -sin
            float cs  = fmaf(qq, fmaf(qq, 1.0f/24.0f, -0.5f), 1.0f);
            Ac[s] = fmaf(cs, r2, -cs);                    // Abar*cos
            As[s] = fmaf(sn, r2, -sn);                    // -Abar*sin
        }
        const float wrap = __shfl_xor_sync(0xffffffffu, h[7], 1);
        h[7] = fmaf(Ac[7], h[7], fmaf(As[7], h[6], db * B1.w));
        h[6] = fmaf(Ac[6], h[6], fmaf(As[6], h[5], db * B1.z));
        h[5] = fmaf(Ac[5], h[5], fmaf(As[5], h[4], db * B1.y));
        h[4] = fmaf(Ac[4], h[4], fmaf(As[4], h[3], db * B1.x));
        h[3] = fmaf(Ac[3], h[3], fmaf(As[3], h[2], db * B0.w));
        h[2] = fmaf(Ac[2], h[2], fmaf(As[2], h[1], db * B0.z));
        h[1] = fmaf(Ac[1], h[1], fmaf(As[1], h[0], db * B0.y));
        h[0] = fmaf(Ac[0], h[0], fmaf(As[0], wrap, db * B0.x));
    };

    auto emit_y = [&](const float* rec, int m) {
        float4 C0 = *(const float4*)(rec + 48 + p * 8);
        float4 C1 = *(const float4*)(rec + 52 + p * 8);
        float y0 = C0.x * h[0];
        float y1 = C0.y * h[1];
        y0 = fmaf(C0.z, h[2], y0);
        y1 = fmaf(C0.w, h[3], y1);
        y0 = fmaf(C1.x, h[4], y0);
        y1 = fmaf(C1.y, h[5], y1);
        y0 = fmaf(C1.z, h[6], y0);
        y1 = fmaf(C1.w, h[7], y1);
        float y = y0 + y1;
        y += __shfl_xor_sync(0xffffffffu, y, 1);
        if (p == 0) sy[w][m * 17 + ch] = y;
    };

    if (mainlen == CHUNK) {
        // fast path: full chunk, double-buffered cp.async pipeline
        const int ntiles = warmtiles + CHUNK / TILE;     // 8 or 12
        stage(0, t_begin);
        for (int k = 0; k < ntiles; k++) {
            if (k + 1 < ntiles) {
                stage((k + 1) & 1, t_begin + (k + 1) * TILE);
                cp_wait<1>();
            } else {
                cp_wait<0>();
            }
            __syncwarp();
            float4 (*tl)[16] = stile[w][k & 1];
            if (k < warmtiles) {
                #pragma unroll
                for (int i = 0; i < TILE; ++i) step_h((const float*)tl[i]);
            } else {
                const int mbase = (k - warmtiles) * TILE;
                #pragma unroll
                for (int i = 0; i < TILE; ++i) {
                    step_h((const float*)tl[i]);
                    emit_y((const float*)tl[i], mbase + i);
                }
            }
        }
    } else {
        // generic tail (N not a multiple of CHUNK): synchronous guarded tiles
        float4 (*tl)[16] = stile[w][0];
        const int warmlen = warmtiles * TILE;
        const int len = warmlen + mainlen;
        for (int k0 = 0; k0 < len; k0 += TILE) {
            int cnt = len - k0; if (cnt > TILE) cnt = TILE;
            const float4* src_d = (const float4*)(g_dtxb + (size_t)(t_begin + k0) * 16);
            const float4* src_B = (const float4*)(g_B    + (size_t)(t_begin + k0) * 16);
            const float4* src_C = (const float4*)(g_C    + (size_t)(t_begin + k0) * 16);
            __syncwarp();
            for (int r = 0; r < 2; r++) {
                int idx = lane + 32 * r;
                if (idx < cnt * 8) tl[idx >> 3][idx & 7] = __ldg(src_d + idx);
            }
            if (lane < cnt * 4) {
                tl[lane >> 2][8  + (lane & 3)] = __ldg(src_B + lane);
                tl[lane >> 2][12 + (lane & 3)] = __ldg(src_C + lane);
            }
            __syncwarp();
            for (int i = 0; i < cnt; ++i) {
                step_h((const float*)tl[i]);
                int m = k0 + i - warmlen;
                if (m >= 0) emit_y((const float*)tl[i], m);
            }
        }
    }

    // ---- final state ----
    if (write_hfinal && chunk == nchunks - 1) {
        float* o = d_out + (size_t)N * 8 + cidx;
        ((float4*)o)[0] = make_float4(h[0], h[1], h[2], h[3]);
        ((float4*)o)[1] = make_float4(h[4], h[5], h[6], h[7]);
    }

    __syncwarp();

    // ---- warp-private fused output projection ----
    for (int tt = lane; tt < mainlen; tt += 32) {
        int t = t_main + tt;
        const float4* z4 = (const float4*)(g_zx + (size_t)t * 16);
        const float* syr = &sy[w][tt * 17];
        float v[16];
        #pragma unroll
        for (int q = 0; q < 4; q++) {
            float4 za = __ldg(z4 + 2 * q);
            float4 zb = __ldg(z4 + 2 * q + 1);
            v[4*q+0] = fmaf(syr[4*q+0], za.x, za.y);
            v[4*q+1] = fmaf(syr[4*q+1], za.z, za.w);
            v[4*q+2] = fmaf(syr[4*q+2], zb.x, zb.y);
            v[4*q+3] = fmaf(syr[4*q+3], zb.z, zb.w);
        }
        float o[8];
        #pragma unroll
        for (int d = 0; d < 8; d++) {
            float acc = 0.f;
            #pragma unroll
            for (int q = 0; q < 4; q++) {
                float4 wr = ((const float4*)sow)[d * 4 + q];
                acc = fmaf(wr.x, v[4*q+0], fmaf(wr.y, v[4*q+1],
                      fmaf(wr.z, v[4*q+2], fmaf(wr.w, v[4*q+3], acc))));
            }
            o[d] = acc;
        }
        ((float4*)(d_out + (size_t)t * 8))[0] = make_float4(o[0], o[1], o[2], o[3]);
        ((float4*)(d_out + (size_t)t * 8))[1] = make_float4(o[4], o[5], o[6], o[7]);
    }
}

// ---------------------------------------------------------------------------
extern "C" void kernel_launch(void* const* d_in, const int* in_sizes, int n_in,
                              void* d_out, int out_size)
{
    const float* x    = (const float*)d_in[0];
    const float* h0   = (const float*)d_in[1];
    const float* inw  = (const float*)d_in[2];
    const float* dtw  = (const float*)d_in[3];
    const float* dtb  = (const float*)d_in[4];
    const float* Bw   = (const float*)d_in[5];
    const float* Cw   = (const float*)d_in[6];
    const float* Alog = (const float*)d_in[7];
    const float* Dp   = (const float*)d_in[8];
    const float* rf   = (const float*)d_in[9];
    const float* ow   = (const float*)d_in[10];

    int N = in_sizes[0] / 8;
    if (N > MAXN) N = MAXN;
    int nchunks = (N + CHUNK - 1) / CHUNK;
    int write_hfinal = (out_size >= N * 8 + 256) ? 1 : 0;

    prep_kernel<<<(N / 2 + 255) / 256, 256>>>(x, inw, dtw, dtb, Bw, Cw, Dp, N);
    scan_kernel<<<(nchunks + WPB - 1) / WPB, 32 * WPB>>>(Alog, rf, h0, ow,
                                                         (float*)d_out, N, nchunks, write_hfinal);
}